// round 7
// baseline (speedup 1.0000x reference)
#include <cuda_runtime.h>
#include <cuda_bf16.h>

// Zero-initialized device scratch. The last block resets these after use,
// so every graph replay sees a clean state (no init kernel needed).
__device__ unsigned int g_hist[64];
__device__ unsigned int g_done = 0;

// 256-bit global load (Blackwell sm_100+/103a, PTX 8.8), non-coherent path.
__device__ __forceinline__ void ldg256(const float* __restrict__ p,
                                       float& r0, float& r1, float& r2, float& r3,
                                       float& r4, float& r5, float& r6, float& r7) {
    asm volatile("ld.global.nc.v8.f32 {%0,%1,%2,%3,%4,%5,%6,%7}, [%8];"
                 : "=f"(r0), "=f"(r1), "=f"(r2), "=f"(r3),
                   "=f"(r4), "=f"(r5), "=f"(r6), "=f"(r7)
                 : "l"(p));
}

// 256-bit global store, evict-first (streaming).
__device__ __forceinline__ void stg256(float* __restrict__ p,
                                       float r0, float r1, float r2, float r3,
                                       float r4, float r5, float r6, float r7) {
    asm volatile("st.global.cs.v8.f32 [%0], {%1,%2,%3,%4,%5,%6,%7,%8};"
                 :: "l"(p),
                    "f"(r0), "f"(r1), "f"(r2), "f"(r3),
                    "f"(r4), "f"(r5), "f"(r6), "f"(r7)
                 : "memory");
}

// ---------------------------------------------------------------------------
// Fast path: T == 4, step divisible by 8. 256-bit vectorized fused copy +
// collector histogram + in-kernel finalize (last-block pattern).
// Per thread per iter: 4 x LDG.256 + 4 x STG.256 (128B in flight / thread).
// ---------------------------------------------------------------------------
__global__ void __launch_bounds__(256, 4)
sparsity_fused_t4_v8(const float* __restrict__ in,
                     float* __restrict__ out,
                     long long step8,
                     long long n, long long step) {
    unsigned int h0 = 0, h1 = 0, h2 = 0, h3 = 0, h4 = 0;
    const long long NT = (long long)gridDim.x * blockDim.x;

    for (long long j = (long long)blockIdx.x * blockDim.x + threadIdx.x;
         j < step8; j += NT) {
        const long long off = j << 3;  // float offset within one time stream
        float a0,a1,a2,a3,a4,a5,a6,a7;
        float b0,b1,b2,b3,b4,b5,b6,b7;
        float c0,c1,c2,c3,c4,c5,c6,c7;
        float d0,d1,d2,d3,d4,d5,d6,d7;
        ldg256(in + off,            a0,a1,a2,a3,a4,a5,a6,a7);
        ldg256(in + step + off,     b0,b1,b2,b3,b4,b5,b6,b7);
        ldg256(in + 2 * step + off, c0,c1,c2,c3,c4,c5,c6,c7);
        ldg256(in + 3 * step + off, d0,d1,d2,d3,d4,d5,d6,d7);

        stg256(out + off,            a0,a1,a2,a3,a4,a5,a6,a7);
        stg256(out + step + off,     b0,b1,b2,b3,b4,b5,b6,b7);
        stg256(out + 2 * step + off, c0,c1,c2,c3,c4,c5,c6,c7);
        stg256(out + 3 * step + off, d0,d1,d2,d3,d4,d5,d6,d7);

        // collector values are exact small integers 0..4 in fp32
        int s0 = (int)(a0 + b0 + c0 + d0);
        int s1 = (int)(a1 + b1 + c1 + d1);
        int s2 = (int)(a2 + b2 + c2 + d2);
        int s3 = (int)(a3 + b3 + c3 + d3);
        int s4 = (int)(a4 + b4 + c4 + d4);
        int s5 = (int)(a5 + b5 + c5 + d5);
        int s6 = (int)(a6 + b6 + c6 + d6);
        int s7 = (int)(a7 + b7 + c7 + d7);
        h0 += (s0==0)+(s1==0)+(s2==0)+(s3==0)+(s4==0)+(s5==0)+(s6==0)+(s7==0);
        h1 += (s0==1)+(s1==1)+(s2==1)+(s3==1)+(s4==1)+(s5==1)+(s6==1)+(s7==1);
        h2 += (s0==2)+(s1==2)+(s2==2)+(s3==2)+(s4==2)+(s5==2)+(s6==2)+(s7==2);
        h3 += (s0==3)+(s1==3)+(s2==3)+(s3==3)+(s4==3)+(s5==3)+(s6==3)+(s7==3);
        h4 += (s0==4)+(s1==4)+(s2==4)+(s3==4)+(s4==4)+(s5==4)+(s6==4)+(s7==4);
    }

    __shared__ unsigned int sh[5];
    if (threadIdx.x < 5) sh[threadIdx.x] = 0u;
    __syncthreads();
    // warp-reduce first to cut shared-atomic traffic 32x
    for (int off = 16; off > 0; off >>= 1) {
        h0 += __shfl_down_sync(0xFFFFFFFFu, h0, off);
        h1 += __shfl_down_sync(0xFFFFFFFFu, h1, off);
        h2 += __shfl_down_sync(0xFFFFFFFFu, h2, off);
        h3 += __shfl_down_sync(0xFFFFFFFFu, h3, off);
        h4 += __shfl_down_sync(0xFFFFFFFFu, h4, off);
    }
    if ((threadIdx.x & 31) == 0) {
        atomicAdd(&sh[0], h0);
        atomicAdd(&sh[1], h1);
        atomicAdd(&sh[2], h2);
        atomicAdd(&sh[3], h3);
        atomicAdd(&sh[4], h4);
    }
    __syncthreads();
    if (threadIdx.x < 5) atomicAdd(&g_hist[threadIdx.x], sh[threadIdx.x]);

    // --- last-block finalize ---
    __threadfence();
    __shared__ bool is_last;
    if (threadIdx.x == 0) {
        unsigned int prev = atomicAdd(&g_done, 1u);
        is_last = (prev == gridDim.x - 1);
    }
    __syncthreads();
    if (is_last && threadIdx.x == 0) {
        unsigned int c0 = g_hist[0], c1 = g_hist[1], c2 = g_hist[2],
                     c3 = g_hist[3], c4 = g_hist[4];
        unsigned long long ones = (unsigned long long)c1
                                + 2ull * c2 + 3ull * c3 + 4ull * c4;
        double zeros = (double)n - (double)ones;
        out[n]     = (float)(zeros / (double)n);          // sparsity_ratio
        out[n + 1] = (float)((double)c0 / (double)step);  // coll zero frac
        out[n + 2] = (float)c0;
        out[n + 3] = (float)c1;
        out[n + 4] = (float)c2;
        out[n + 5] = (float)c3;
        out[n + 6] = (float)c4;
        // reset scratch for next (graph-replayed) launch
        g_hist[0] = 0u; g_hist[1] = 0u; g_hist[2] = 0u;
        g_hist[3] = 0u; g_hist[4] = 0u;
        g_done = 0u;
    }
}

// ---------------------------------------------------------------------------
// Generic fallback: any T (<= 63), any step. Scalar loads, shared-atomic
// histogram, same last-block finalize.
// ---------------------------------------------------------------------------
__global__ void sparsity_fused_generic(const float* __restrict__ in,
                                       float* __restrict__ out,
                                       long long step, int T, long long n) {
    extern __shared__ unsigned int shh[];
    for (int k = threadIdx.x; k <= T; k += blockDim.x) shh[k] = 0u;
    __syncthreads();

    const long long stride = (long long)gridDim.x * blockDim.x;
    for (long long j = (long long)blockIdx.x * blockDim.x + threadIdx.x;
         j < step; j += stride) {
        float c = 0.f;
        for (int t = 0; t < T; t++) {
            const long long idx = (long long)t * step + j;
            float v = in[idx];
            out[idx] = v;
            c += v;
        }
        atomicAdd(&shh[(int)c], 1u);
    }
    __syncthreads();
    for (int k = threadIdx.x; k <= T; k += blockDim.x)
        atomicAdd(&g_hist[k], shh[k]);

    __threadfence();
    __shared__ bool is_last;
    if (threadIdx.x == 0) {
        unsigned int prev = atomicAdd(&g_done, 1u);
        is_last = (prev == gridDim.x - 1);
    }
    __syncthreads();
    if (is_last && threadIdx.x == 0) {
        unsigned long long ones = 0ull;
        for (int k = 1; k <= T; k++)
            ones += (unsigned long long)k * (unsigned long long)g_hist[k];
        double zeros = (double)n - (double)ones;
        out[n]     = (float)(zeros / (double)n);
        out[n + 1] = (float)((double)g_hist[0] / (double)step);
        for (int k = 0; k <= T; k++) {
            out[n + 2 + k] = (float)g_hist[k];
            g_hist[k] = 0u;
        }
        g_done = 0u;
    }
}

extern "C" void kernel_launch(void* const* d_in, const int* in_sizes, int n_in,
                              void* d_out, int out_size) {
    const float* spikes = (const float*)d_in[0];
    float* out = (float*)d_out;
    const long long n = (long long)in_sizes[0];

    // out_size = n + 1 + 1 + (T+1)  =>  T = out_size - n - 3
    long long T_ll = (long long)out_size - n - 3;
    int T = (T_ll >= 1 && T_ll <= 63 && (n % T_ll) == 0) ? (int)T_ll : 4;
    const long long step = n / T;

    const int threads = 256;
    if (T == 4 && (step % 8) == 0) {
        const long long step8 = step / 8;
        // Single full wave: 4 CTAs/SM (pinned by __launch_bounds__) x 148 SMs.
        int blocks = 148 * 4;
        long long maxb = (step8 + threads - 1) / threads;
        if ((long long)blocks > maxb) blocks = (int)maxb;
        if (blocks < 1) blocks = 1;
        sparsity_fused_t4_v8<<<blocks, threads>>>(
            spikes, out, step8, n, step);
    } else {
        int blocks = 148 * 8;
        long long maxb = (step + threads - 1) / threads;
        if ((long long)blocks > maxb) blocks = (int)maxb;
        if (blocks < 1) blocks = 1;
        sparsity_fused_generic<<<blocks, threads, (T + 1) * sizeof(unsigned int)>>>(
            spikes, out, step, T, n);
    }
}